// round 8
// baseline (speedup 1.0000x reference)
#include <cuda_runtime.h>
#include <cuda_bf16.h>
#include <cstdint>

// T=8 tables, N=500000 rows/table, D=64, B=16384 bags/table, L=20.
// indices [T*B*L] int32 (global row ids), offsets [T*B] int32,
// weights [T*N*D] f32. Output [B, T*D] f32.
//
// One warp per PAIR of adjacent bags. lanes 0-15 -> even rows, lanes
// 16-31 -> odd rows, float4/lane => 512B per gather instruction. All 20
// gathers (2 bags x 10) flow through ONE 6-deep cp.async.cg smem ring, so
// bag0's tail drain is overlapped by bag1's in-flight gathers: one full
// drain per pair instead of per bag. Output via st.global.cs (streaming).

#define EMB_D 64
#define EMB_T 8
#define STAGES 6

__device__ __forceinline__ void cp_wait(int n) {
    switch (n) {
        case 0: asm volatile("cp.async.wait_group 0;" ::: "memory"); break;
        case 1: asm volatile("cp.async.wait_group 1;" ::: "memory"); break;
        case 2: asm volatile("cp.async.wait_group 2;" ::: "memory"); break;
        case 3: asm volatile("cp.async.wait_group 3;" ::: "memory"); break;
        case 4: asm volatile("cp.async.wait_group 4;" ::: "memory"); break;
        default: asm volatile("cp.async.wait_group 5;" ::: "memory"); break;
    }
}

__device__ __forceinline__ void cp_issue(unsigned int smem_dst, const float* gsrc) {
    asm volatile("cp.async.cg.shared.global [%0], [%1], 16;\n"
                 "cp.async.commit_group;\n" :: "r"(smem_dst), "l"(gsrc)
                 : "memory");
}

__device__ __forceinline__ void stg_cs_v4(float* p, float4 v) {
    asm volatile("st.global.cs.v4.f32 [%0], {%1, %2, %3, %4};"
                 :: "l"(p), "f"(v.x), "f"(v.y), "f"(v.z), "f"(v.w)
                 : "memory");
}

__device__ __forceinline__ void bag_generic(
    const int* __restrict__ indices, const float* __restrict__ weights,
    int start, int count, int lane, int half, int colbase, float4& acc)
{
    for (int base = 0; base < count; base += 32) {
        int m = min(32, count - base);
        int il = (lane < m) ? __ldg(indices + start + base + lane) : 0;
        int it = 0;
        for (; it + 2 <= m; it += 2) {
            int rr = __shfl_sync(0xffffffffu, il, it + half);
            const float4 v = __ldg(reinterpret_cast<const float4*>(
                weights + (size_t)rr * EMB_D + colbase));
            acc.x += v.x; acc.y += v.y; acc.z += v.z; acc.w += v.w;
        }
        if (it < m) {
            int rr = __shfl_sync(0xffffffffu, il, it);
            if (half == 0) {
                const float4 v = __ldg(reinterpret_cast<const float4*>(
                    weights + (size_t)rr * EMB_D + colbase));
                acc.x += v.x; acc.y += v.y; acc.z += v.z; acc.w += v.w;
            }
        }
    }
}

__device__ __forceinline__ void reduce_store(
    float4 acc, int count, float* dst)
{
    acc.x += __shfl_xor_sync(0xffffffffu, acc.x, 16);
    acc.y += __shfl_xor_sync(0xffffffffu, acc.y, 16);
    acc.z += __shfl_xor_sync(0xffffffffu, acc.z, 16);
    acc.w += __shfl_xor_sync(0xffffffffu, acc.w, 16);
    float inv = 1.0f / fmaxf((float)count, 1.0f);
    float4 o = make_float4(acc.x * inv, acc.y * inv, acc.z * inv, acc.w * inv);
    stg_cs_v4(dst, o);
}

__global__ __launch_bounds__(256, 7) void embbag_mean_pair_kernel(
    const int* __restrict__ indices,
    const int* __restrict__ offsets,
    const float* __restrict__ weights,
    float* __restrict__ out,
    int num_bags,            // T*B
    int bags_per_table,      // B
    int idx_per_table)       // B*L
{
    __shared__ __align__(16) float4 pipe_buf[8][STAGES][32];  // 24 KB

    int gwarp = (blockIdx.x * blockDim.x + threadIdx.x) >> 5;
    int lane  = threadIdx.x & 31;
    int wib   = threadIdx.x >> 5;

    int bag0 = gwarp * 2;
    if (bag0 >= num_bags) return;
    int bag1 = bag0 + 1;                 // same table (bags_per_table even)

    int t = bag0 / bags_per_table;
    int b0 = bag0 - t * bags_per_table;

    int start0 = __ldg(offsets + bag0);
    int start1 = __ldg(offsets + bag1);
    int end1   = (b0 + 1 == bags_per_table - 1) ? (t + 1) * idx_per_table
                                                : __ldg(offsets + bag1 + 1);
    int count0 = start1 - start0;
    int count1 = end1 - start1;

    const int half    = lane >> 4;          // 0: even rows, 1: odd rows
    const int colbase = (lane & 15) << 2;   // float4 column offset

    float* dst0 = out + (size_t)b0 * (EMB_T * EMB_D) + t * EMB_D + colbase;
    float* dst1 = dst0 + (EMB_T * EMB_D);

    float4 acc = make_float4(0.f, 0.f, 0.f, 0.f);

    if (count0 == 20 && count1 == 20) {
        int idx0 = (lane < 20) ? __ldg(indices + start0 + lane) : 0;
        int idx1 = (lane < 20) ? __ldg(indices + start1 + lane) : 0;

        unsigned int sb =
            (unsigned int)__cvta_generic_to_shared(&pipe_buf[wib][0][lane]);

        // Row id for gather j (0..19): bag0 rows then bag1 rows.
        #define RID(j) ((j) < 10 ? __shfl_sync(0xffffffffu, idx0, 2*(j) + half) \
                                 : __shfl_sync(0xffffffffu, idx1, 2*((j)-10) + half))

        // Prologue: fill ring.
        #pragma unroll
        for (int s = 0; s < STAGES; ++s) {
            int r = RID(s);
            cp_issue(sb + s * 512u, weights + (size_t)r * EMB_D + colbase);
        }

        #pragma unroll
        for (int j = 0; j < 20; ++j) {
            cp_wait(min(STAGES - 1, 19 - j));
            float4 v = pipe_buf[wib][j % STAGES][lane];
            acc.x += v.x; acc.y += v.y; acc.z += v.z; acc.w += v.w;
            if (j + STAGES < 20) {
                int r = RID(j + STAGES);
                cp_issue(sb + ((j + STAGES) % STAGES) * 512u,
                         weights + (size_t)r * EMB_D + colbase);
            }
            if (j == 9) {
                reduce_store(acc, 20, dst0);   // bag1 gathers still in flight
                acc = make_float4(0.f, 0.f, 0.f, 0.f);
            }
        }
        #undef RID
        reduce_store(acc, 20, dst1);
    } else {
        // Generic path (any bag lengths).
        bag_generic(indices, weights, start0, count0, lane, half, colbase, acc);
        reduce_store(acc, count0, dst0);
        acc = make_float4(0.f, 0.f, 0.f, 0.f);
        bag_generic(indices, weights, start1, count1, lane, half, colbase, acc);
        reduce_store(acc, count1, dst1);
    }
}

extern "C" void kernel_launch(void* const* d_in, const int* in_sizes, int n_in,
                              void* d_out, int out_size) {
    const int*   indices = (const int*)d_in[0];
    const int*   offsets = (const int*)d_in[1];
    const float* weights = (const float*)d_in[2];
    float*       out     = (float*)d_out;

    int num_bags       = in_sizes[1];          // T*B = 131072
    int bags_per_table = num_bags / EMB_T;     // B
    int idx_per_table  = in_sizes[0] / EMB_T;  // B*L

    int num_pairs = (num_bags + 1) / 2;        // 65536
    int threads = 256;                          // 8 warps/block
    int blocks = (num_pairs * 32 + threads - 1) / threads;

    embbag_mean_pair_kernel<<<blocks, threads>>>(indices, offsets, weights, out,
                                                 num_bags, bags_per_table,
                                                 idx_per_table);
}